// round 1
// baseline (speedup 1.0000x reference)
#include <cuda_runtime.h>
#include <math.h>

// ---------------- problem constants ----------------
#define SEQ   3072
#define DIM   768
#define NHEAD 16
#define HDIM  48
#define DFF   3072
#define NLAYER 6
#define NTOK  1024
#define IMGSZ 256

// ---------------- scratch buffers (static, allocation-free) ----------------
__device__ float d_x   [SEQ * DIM];
__device__ float d_h   [SEQ * DIM];
__device__ float d_qkv [SEQ * 3 * DIM];
__device__ float d_o   [SEQ * DIM];
__device__ float d_f   [SEQ * DFF];
__device__ float d_xinref[2048 * 576];
__device__ float d_xintar[1024 * 384];
__device__ float d_rays[3 * IMGSZ * IMGSZ * 6];
__device__ float d_M   [3 * 16];
__device__ float d_Minv[3 * 16];
__device__ float d_proj[1024 * 192];

// ---------------- camera matrices ----------------
__global__ void cams_kernel(const float* __restrict__ ref_c2w,
                            const float* __restrict__ tar_c2w) {
    int v = threadIdx.x;
    if (v >= 3) return;
    const float* c = (v < 2) ? (ref_c2w + v * 16) : tar_c2w;
    for (int i = 0; i < 16; i++) d_Minv[v * 16 + i] = c[i];
    float* M = d_M + v * 16;
    // M = inv(c2w) = [R^T, -R^T t; 0 0 0 1]
    for (int i = 0; i < 3; i++)
        for (int j = 0; j < 3; j++)
            M[i * 4 + j] = c[j * 4 + i];
    float t0 = c[3], t1 = c[7], t2 = c[11];
    for (int i = 0; i < 3; i++)
        M[i * 4 + 3] = -(c[i] * t0 + c[4 + i] * t1 + c[8 + i] * t2);
    M[12] = 0.f; M[13] = 0.f; M[14] = 0.f; M[15] = 1.f;
}

// ---------------- Plucker rays ----------------
__global__ void rays_kernel(const float* __restrict__ ref_c2w,
                            const float* __restrict__ ref_K,
                            const float* __restrict__ tar_c2w,
                            const float* __restrict__ tar_K) {
    int idx = blockIdx.x * 256 + threadIdx.x;   // 3 * 65536
    if (idx >= 3 * IMGSZ * IMGSZ) return;
    int v = idx >> 16;
    int p = idx & 65535;
    int h = p >> 8, w = p & 255;
    const float* c2w = (v < 2) ? (ref_c2w + v * 16) : tar_c2w;
    const float* K   = (v < 2) ? (ref_K + v * 9)    : tar_K;
    float fx = K[0], cx = K[2], fy = K[4], cy = K[5];
    // d_cam = K^-1 @ [w+0.5, h+0.5, 1]
    float dx = ((float)w + 0.5f - cx) / fx;
    float dy = ((float)h + 0.5f - cy) / fy;
    float dz = 1.0f;
    // d = R @ d_cam
    float d0 = c2w[0] * dx + c2w[1] * dy + c2w[2]  * dz;
    float d1 = c2w[4] * dx + c2w[5] * dy + c2w[6]  * dz;
    float d2 = c2w[8] * dx + c2w[9] * dy + c2w[10] * dz;
    float inv = rsqrtf(d0 * d0 + d1 * d1 + d2 * d2);
    d0 *= inv; d1 *= inv; d2 *= inv;
    float o0 = c2w[3], o1 = c2w[7], o2 = c2w[11];
    float m0 = o1 * d2 - o2 * d1;
    float m1 = o2 * d0 - o0 * d2;
    float m2 = o0 * d1 - o1 * d0;
    float* r = d_rays + (size_t)idx * 6;
    r[0] = d0; r[1] = d1; r[2] = d2; r[3] = m0; r[4] = m1; r[5] = m2;
}

// ---------------- patchified input assembly ----------------
__global__ void xinref_kernel(const float* __restrict__ imgs) {
    int idx = blockIdx.x * 256 + threadIdx.x;
    if (idx >= 2048 * 576) return;
    int tok = idx / 576, f = idx % 576;
    int v = tok >> 10, n = tok & 1023;
    int pr = n >> 5, pc = n & 31;
    float val;
    if (f < 192) {
        int ch = f % 3, pp = f / 3;
        int pi = pp >> 3, pj = pp & 7;
        int h = pr * 8 + pi, w = pc * 8 + pj;
        val = imgs[((size_t)(v * IMGSZ + h) * IMGSZ + w) * 3 + ch];
    } else {
        int f2 = f - 192;
        int ch = f2 % 6, pp = f2 / 6;
        int pi = pp >> 3, pj = pp & 7;
        int h = pr * 8 + pi, w = pc * 8 + pj;
        val = d_rays[((size_t)v * 65536 + h * 256 + w) * 6 + ch];
    }
    d_xinref[idx] = val;
}

__global__ void xintar_kernel() {
    int idx = blockIdx.x * 256 + threadIdx.x;
    if (idx >= 1024 * 384) return;
    int tok = idx / 384, f = idx % 384;
    int pr = tok >> 5, pc = tok & 31;
    int ch = f % 6, pp = f / 6;
    int pi = pp >> 3, pj = pp & 7;
    int h = pr * 8 + pi, w = pc * 8 + pj;
    d_xintar[idx] = d_rays[((size_t)2 * 65536 + h * 256 + w) * 6 + ch];
}

// ---------------- LayerNorm ----------------
__device__ __forceinline__ float block_sum(float v) {
    __shared__ float red[32];
    int lane = threadIdx.x & 31, wid = threadIdx.x >> 5;
#pragma unroll
    for (int o = 16; o; o >>= 1) v += __shfl_xor_sync(0xffffffffu, v, o);
    if (lane == 0) red[wid] = v;
    __syncthreads();
    if (wid == 0) {
        float r = (lane < 8) ? red[lane] : 0.f;
#pragma unroll
        for (int o = 4; o; o >>= 1) r += __shfl_xor_sync(0xffffffffu, r, o);
        if (lane == 0) red[0] = r;
    }
    __syncthreads();
    float out = red[0];
    __syncthreads();   // guard against reuse of red[] in a subsequent call
    return out;
}

__global__ void ln_kernel(const float* __restrict__ x, const float* __restrict__ g,
                          float* __restrict__ out) {
    int s = blockIdx.x;
    const float* xr = x + (size_t)s * DIM;
    int t = threadIdx.x;
    float v0 = xr[t], v1 = xr[t + 256], v2 = xr[t + 512];
    float mu = block_sum(v0 + v1 + v2) * (1.0f / DIM);
    float e0 = v0 - mu, e1 = v1 - mu, e2 = v2 - mu;
    float var = block_sum(e0 * e0 + e1 * e1 + e2 * e2) * (1.0f / DIM);
    float rstd = rsqrtf(var + 1e-5f);
    float* orow = out + (size_t)s * DIM;
    orow[t]       = e0 * rstd * g[t];
    orow[t + 256] = e1 * rstd * g[t + 256];
    orow[t + 512] = e2 * rstd * g[t + 512];
}

// ---------------- SGEMM: C[M,N] (op)= A[M,K] @ B[N,K]^T ----------------
// 128x128 tile, BK=16, 256 threads, 8x8 per thread
__global__ __launch_bounds__(256, 2)
void sgemm128(const float* __restrict__ A, const float* __restrict__ B,
              float* __restrict__ C, int M, int N, int K, int accum, int relu) {
    __shared__ float As[16][132];
    __shared__ float Bs[16][132];
    int bm = blockIdx.y << 7, bn = blockIdx.x << 7;
    int tid = threadIdx.x;
    int tx = tid & 15, ty = tid >> 4;
    float acc[8][8];
#pragma unroll
    for (int i = 0; i < 8; i++)
#pragma unroll
        for (int j = 0; j < 8; j++) acc[i][j] = 0.f;
    const float* Ab = A + (size_t)bm * K;
    const float* Bb = B + (size_t)bn * K;
    for (int k0 = 0; k0 < K; k0 += 16) {
        __syncthreads();
#pragma unroll
        for (int f = tid; f < 512; f += 256) {
            int row = f >> 2, kq = (f & 3) << 2;
            float4 a = *(const float4*)(Ab + (size_t)row * K + k0 + kq);
            As[kq + 0][row] = a.x; As[kq + 1][row] = a.y;
            As[kq + 2][row] = a.z; As[kq + 3][row] = a.w;
            float4 b = *(const float4*)(Bb + (size_t)row * K + k0 + kq);
            Bs[kq + 0][row] = b.x; Bs[kq + 1][row] = b.y;
            Bs[kq + 2][row] = b.z; Bs[kq + 3][row] = b.w;
        }
        __syncthreads();
#pragma unroll
        for (int k = 0; k < 16; k++) {
            float4 a0 = *(const float4*)&As[k][ty * 8];
            float4 a1 = *(const float4*)&As[k][ty * 8 + 4];
            float4 b0 = *(const float4*)&Bs[k][tx * 8];
            float4 b1 = *(const float4*)&Bs[k][tx * 8 + 4];
            float av[8] = {a0.x, a0.y, a0.z, a0.w, a1.x, a1.y, a1.z, a1.w};
            float bv[8] = {b0.x, b0.y, b0.z, b0.w, b1.x, b1.y, b1.z, b1.w};
#pragma unroll
            for (int i = 0; i < 8; i++)
#pragma unroll
                for (int j = 0; j < 8; j++) acc[i][j] += av[i] * bv[j];
        }
    }
#pragma unroll
    for (int i = 0; i < 8; i++) {
        float* cp = C + (size_t)(bm + ty * 8 + i) * N + bn + tx * 8;
#pragma unroll
        for (int j = 0; j < 8; j++) {
            float v = acc[i][j];
            if (relu) v = fmaxf(v, 0.f);
            if (accum) v += cp[j];
            cp[j] = v;
        }
    }
}

// 64x64 tile variant for N=192 projection
__global__ __launch_bounds__(256)
void sgemm64(const float* __restrict__ A, const float* __restrict__ B,
             float* __restrict__ C, int M, int N, int K) {
    __shared__ float As[16][68];
    __shared__ float Bs[16][68];
    int bm = blockIdx.y << 6, bn = blockIdx.x << 6;
    int tid = threadIdx.x;
    int tx = tid & 15, ty = tid >> 4;
    float acc[4][4];
#pragma unroll
    for (int i = 0; i < 4; i++)
#pragma unroll
        for (int j = 0; j < 4; j++) acc[i][j] = 0.f;
    int row = tid >> 2, kq = (tid & 3) << 2;
    const float* Ab = A + (size_t)bm * K;
    const float* Bb = B + (size_t)bn * K;
    for (int k0 = 0; k0 < K; k0 += 16) {
        __syncthreads();
        float4 a = *(const float4*)(Ab + (size_t)row * K + k0 + kq);
        As[kq + 0][row] = a.x; As[kq + 1][row] = a.y;
        As[kq + 2][row] = a.z; As[kq + 3][row] = a.w;
        float4 b = *(const float4*)(Bb + (size_t)row * K + k0 + kq);
        Bs[kq + 0][row] = b.x; Bs[kq + 1][row] = b.y;
        Bs[kq + 2][row] = b.z; Bs[kq + 3][row] = b.w;
        __syncthreads();
#pragma unroll
        for (int k = 0; k < 16; k++) {
            float4 a4 = *(const float4*)&As[k][ty * 4];
            float4 b4 = *(const float4*)&Bs[k][tx * 4];
            float av[4] = {a4.x, a4.y, a4.z, a4.w};
            float bv[4] = {b4.x, b4.y, b4.z, b4.w};
#pragma unroll
            for (int i = 0; i < 4; i++)
#pragma unroll
                for (int j = 0; j < 4; j++) acc[i][j] += av[i] * bv[j];
        }
    }
#pragma unroll
    for (int i = 0; i < 4; i++) {
        float* cp = C + (size_t)(bm + ty * 4 + i) * N + bn + tx * 4;
#pragma unroll
        for (int j = 0; j < 4; j++) cp[j] = acc[i][j];
    }
}

// ---------------- per-token 4x4 camera transform ----------------
__global__ void camtf_kernel(float* __restrict__ x, const float* __restrict__ Mb,
                             int ncols) {
    int ng = ncols >> 2;
    int idx = blockIdx.x * 256 + threadIdx.x;
    if (idx >= SEQ * ng) return;
    int s = idx / ng, g = idx % ng;
    const float* M = Mb + (size_t)(s >> 10) * 16;
    float4 v = *(float4*)(x + (size_t)s * ncols + g * 4);
    float y0 = M[0]  * v.x + M[1]  * v.y + M[2]  * v.z + M[3]  * v.w;
    float y1 = M[4]  * v.x + M[5]  * v.y + M[6]  * v.z + M[7]  * v.w;
    float y2 = M[8]  * v.x + M[9]  * v.y + M[10] * v.z + M[11] * v.w;
    float y3 = M[12] * v.x + M[13] * v.y + M[14] * v.z + M[15] * v.w;
    *(float4*)(x + (size_t)s * ncols + g * 4) = make_float4(y0, y1, y2, y3);
}

// ---------------- attention (online softmax, 1 query/thread) ----------------
__global__ __launch_bounds__(128)
void attn_kernel() {
    int h = blockIdx.y;
    int qi = (blockIdx.x << 7) + threadIdx.x;
    const float scale = 0.14433756729740643f;   // 1/sqrt(48)
    const float* qp = d_qkv + (size_t)qi * (3 * DIM) + h * HDIM;
    float q[HDIM];
#pragma unroll
    for (int d = 0; d < HDIM; d++) q[d] = qp[d] * scale;
    float acc[HDIM];
#pragma unroll
    for (int d = 0; d < HDIM; d++) acc[d] = 0.f;
    float mmax = -1e30f, lsum = 0.f;

    __shared__ float Ks[32][HDIM];
    __shared__ float Vs[32][HDIM];
    const float* kbase = d_qkv + DIM     + h * HDIM;
    const float* vbase = d_qkv + 2 * DIM + h * HDIM;

    for (int kt = 0; kt < SEQ; kt += 32) {
        __syncthreads();
#pragma unroll
        for (int t = threadIdx.x; t < 384; t += 128) {
            int row = t / 12, c4 = (t % 12) * 4;
            *(float4*)&Ks[row][c4] = *(const float4*)(kbase + (size_t)(kt + row) * (3 * DIM) + c4);
            *(float4*)&Vs[row][c4] = *(const float4*)(vbase + (size_t)(kt + row) * (3 * DIM) + c4);
        }
        __syncthreads();
        float logits[32];
        float tmax = mmax;
#pragma unroll 4
        for (int j = 0; j < 32; j++) {
            const float4* kr = (const float4*)Ks[j];
            float sacc = 0.f;
#pragma unroll
            for (int d4 = 0; d4 < 12; d4++) {
                float4 kk = kr[d4];
                sacc += q[d4 * 4]     * kk.x + q[d4 * 4 + 1] * kk.y
                      + q[d4 * 4 + 2] * kk.z + q[d4 * 4 + 3] * kk.w;
            }
            logits[j] = sacc;
            tmax = fmaxf(tmax, sacc);
        }
        float corr = __expf(mmax - tmax);
        lsum *= corr;
#pragma unroll
        for (int d = 0; d < HDIM; d++) acc[d] *= corr;
#pragma unroll 4
        for (int j = 0; j < 32; j++) {
            float p = __expf(logits[j] - tmax);
            lsum += p;
            const float4* vr = (const float4*)Vs[j];
#pragma unroll
            for (int d4 = 0; d4 < 12; d4++) {
                float4 vv = vr[d4];
                acc[d4 * 4]     += p * vv.x;
                acc[d4 * 4 + 1] += p * vv.y;
                acc[d4 * 4 + 2] += p * vv.z;
                acc[d4 * 4 + 3] += p * vv.w;
            }
        }
        mmax = tmax;
    }
    float inv = 1.f / lsum;
    float* op = d_o + (size_t)qi * DIM + h * HDIM;
#pragma unroll
    for (int d = 0; d < HDIM; d++) op[d] = acc[d] * inv;
}

// ---------------- unpatchify ----------------
__global__ void unpatch_kernel(float* __restrict__ out) {
    int idx = blockIdx.x * 256 + threadIdx.x;
    if (idx >= IMGSZ * IMGSZ * 3) return;
    int c = idx % 3;
    int w = (idx / 3) & 255;
    int h = idx / (IMGSZ * 3);
    int n = (h >> 3) * 32 + (w >> 3);
    int f = ((h & 7) * 8 + (w & 7)) * 3 + c;
    out[idx] = d_proj[n * 192 + f];
}

// ---------------- launcher ----------------
extern "C" void kernel_launch(void* const* d_in, const int* in_sizes, int n_in,
                              void* d_out, int out_size) {
    (void)in_sizes; (void)n_in; (void)out_size;
    const float* ref_imgs = (const float*)d_in[0];
    const float* ref_c2w  = (const float*)d_in[1];
    const float* ref_K    = (const float*)d_in[2];
    const float* tar_c2w  = (const float*)d_in[3];
    const float* tar_K    = (const float*)d_in[4];
    const float* W_in     = (const float*)d_in[5];
    const float* W_q      = (const float*)d_in[6];
    const float* W_out    = (const float*)d_in[7];
    const float* gin      = (const float*)d_in[8];
    const float* gout     = (const float*)d_in[9];
    const float* Wqkv     = (const float*)d_in[10];
    const float* Wo       = (const float*)d_in[11];
    const float* g1       = (const float*)d_in[12];
    const float* g2       = (const float*)d_in[13];
    const float* W1       = (const float*)d_in[14];
    const float* W2       = (const float*)d_in[15];
    float* out = (float*)d_out;

    float *x, *h, *qkv, *o, *f, *xinref, *xintar, *proj, *M, *Minv;
    cudaGetSymbolAddress((void**)&x,      d_x);
    cudaGetSymbolAddress((void**)&h,      d_h);
    cudaGetSymbolAddress((void**)&qkv,    d_qkv);
    cudaGetSymbolAddress((void**)&o,      d_o);
    cudaGetSymbolAddress((void**)&f,      d_f);
    cudaGetSymbolAddress((void**)&xinref, d_xinref);
    cudaGetSymbolAddress((void**)&xintar, d_xintar);
    cudaGetSymbolAddress((void**)&proj,   d_proj);
    cudaGetSymbolAddress((void**)&M,      d_M);
    cudaGetSymbolAddress((void**)&Minv,   d_Minv);

    cams_kernel<<<1, 3>>>(ref_c2w, tar_c2w);
    rays_kernel<<<768, 256>>>(ref_c2w, ref_K, tar_c2w, tar_K);
    xinref_kernel<<<4608, 256>>>(ref_imgs);
    xintar_kernel<<<1536, 256>>>();

    sgemm128<<<dim3(6, 16), 256>>>(xinref, W_in, x, 2048, DIM, 576, 0, 0);
    sgemm128<<<dim3(6, 8),  256>>>(xintar, W_q,  x + (size_t)2048 * DIM, 1024, DIM, 384, 0, 0);
    ln_kernel<<<SEQ, 256>>>(x, gin, x);

    for (int l = 0; l < NLAYER; l++) {
        ln_kernel<<<SEQ, 256>>>(x, g1 + (size_t)l * DIM, h);
        sgemm128<<<dim3(18, 24), 256>>>(h, Wqkv + (size_t)l * 3 * DIM * DIM, qkv,
                                        SEQ, 3 * DIM, DIM, 0, 0);
        camtf_kernel<<<6912, 256>>>(qkv, M, 3 * DIM);
        attn_kernel<<<dim3(24, NHEAD), 128>>>();
        camtf_kernel<<<2304, 256>>>(o, Minv, DIM);
        sgemm128<<<dim3(6, 24), 256>>>(o, Wo + (size_t)l * DIM * DIM, x,
                                       SEQ, DIM, DIM, 1, 0);
        ln_kernel<<<SEQ, 256>>>(x, g2 + (size_t)l * DIM, h);
        sgemm128<<<dim3(24, 24), 256>>>(h, W1 + (size_t)l * DFF * DIM, f,
                                        SEQ, DFF, DIM, 0, 1);
        sgemm128<<<dim3(6, 24), 256>>>(f, W2 + (size_t)l * DIM * DFF, x,
                                       SEQ, DIM, DFF, 1, 0);
    }

    ln_kernel<<<SEQ, 256>>>(x, gout, h);
    sgemm64<<<dim3(3, 16), 256>>>(h + (size_t)2048 * DIM, W_out, proj, 1024, 192, DIM);
    unpatch_kernel<<<768, 256>>>(out);
}

// round 2
// speedup vs baseline: 2.5488x; 2.5488x over previous
#include <cuda_runtime.h>
#include <math.h>

// ---------------- problem constants ----------------
#define SEQ   3072
#define DIM   768
#define NHEAD 16
#define HDIM  48
#define DFF   3072
#define NLAYER 6
#define NTOK  1024
#define IMGSZ 256

// ---------------- scratch buffers (static, allocation-free) ----------------
__device__ float d_x   [SEQ * DIM];
__device__ float d_h   [SEQ * DIM];
__device__ float d_qkv [SEQ * 3 * DIM];
__device__ float d_o   [SEQ * DIM];
__device__ float d_f   [SEQ * DFF];
__device__ float d_xinref[2048 * 576];
__device__ float d_xintar[1024 * 384];
__device__ float d_rays[3 * IMGSZ * IMGSZ * 6];
__device__ float d_M   [3 * 16];
__device__ float d_Minv[3 * 16];
__device__ float d_proj[1024 * 192];

// ---------------- helpers ----------------
__device__ __forceinline__ unsigned f2tf(float f) {
    unsigned u;
    asm("cvt.rna.tf32.f32 %0, %1;" : "=r"(u) : "f"(f));
    return u;
}

__device__ __forceinline__ void mma_tf32(float* c, const unsigned* a, const unsigned* b) {
    asm volatile("mma.sync.aligned.m16n8k8.row.col.f32.tf32.tf32.f32 "
        "{%0,%1,%2,%3}, {%4,%5,%6,%7}, {%8,%9}, {%0,%1,%2,%3};"
        : "+f"(c[0]), "+f"(c[1]), "+f"(c[2]), "+f"(c[3])
        : "r"(a[0]), "r"(a[1]), "r"(a[2]), "r"(a[3]), "r"(b[0]), "r"(b[1]));
}

// ---------------- camera matrices ----------------
__global__ void cams_kernel(const float* __restrict__ ref_c2w,
                            const float* __restrict__ tar_c2w) {
    int v = threadIdx.x;
    if (v >= 3) return;
    const float* c = (v < 2) ? (ref_c2w + v * 16) : tar_c2w;
    for (int i = 0; i < 16; i++) d_Minv[v * 16 + i] = c[i];
    float* M = d_M + v * 16;
    for (int i = 0; i < 3; i++)
        for (int j = 0; j < 3; j++)
            M[i * 4 + j] = c[j * 4 + i];
    float t0 = c[3], t1 = c[7], t2 = c[11];
    for (int i = 0; i < 3; i++)
        M[i * 4 + 3] = -(c[i] * t0 + c[4 + i] * t1 + c[8 + i] * t2);
    M[12] = 0.f; M[13] = 0.f; M[14] = 0.f; M[15] = 1.f;
}

// ---------------- Plucker rays ----------------
__global__ void rays_kernel(const float* __restrict__ ref_c2w,
                            const float* __restrict__ ref_K,
                            const float* __restrict__ tar_c2w,
                            const float* __restrict__ tar_K) {
    int idx = blockIdx.x * 256 + threadIdx.x;
    if (idx >= 3 * IMGSZ * IMGSZ) return;
    int v = idx >> 16;
    int p = idx & 65535;
    int h = p >> 8, w = p & 255;
    const float* c2w = (v < 2) ? (ref_c2w + v * 16) : tar_c2w;
    const float* K   = (v < 2) ? (ref_K + v * 9)    : tar_K;
    float fx = K[0], cx = K[2], fy = K[4], cy = K[5];
    float dx = ((float)w + 0.5f - cx) / fx;
    float dy = ((float)h + 0.5f - cy) / fy;
    float dz = 1.0f;
    float d0 = c2w[0] * dx + c2w[1] * dy + c2w[2]  * dz;
    float d1 = c2w[4] * dx + c2w[5] * dy + c2w[6]  * dz;
    float d2 = c2w[8] * dx + c2w[9] * dy + c2w[10] * dz;
    float inv = rsqrtf(d0 * d0 + d1 * d1 + d2 * d2);
    d0 *= inv; d1 *= inv; d2 *= inv;
    float o0 = c2w[3], o1 = c2w[7], o2 = c2w[11];
    float m0 = o1 * d2 - o2 * d1;
    float m1 = o2 * d0 - o0 * d2;
    float m2 = o0 * d1 - o1 * d0;
    float* r = d_rays + (size_t)idx * 6;
    r[0] = d0; r[1] = d1; r[2] = d2; r[3] = m0; r[4] = m1; r[5] = m2;
}

// ---------------- patchified input assembly ----------------
__global__ void xinref_kernel(const float* __restrict__ imgs) {
    int idx = blockIdx.x * 256 + threadIdx.x;
    if (idx >= 2048 * 576) return;
    int tok = idx / 576, f = idx % 576;
    int v = tok >> 10, n = tok & 1023;
    int pr = n >> 5, pc = n & 31;
    float val;
    if (f < 192) {
        int ch = f % 3, pp = f / 3;
        int pi = pp >> 3, pj = pp & 7;
        int h = pr * 8 + pi, w = pc * 8 + pj;
        val = imgs[((size_t)(v * IMGSZ + h) * IMGSZ + w) * 3 + ch];
    } else {
        int f2 = f - 192;
        int ch = f2 % 6, pp = f2 / 6;
        int pi = pp >> 3, pj = pp & 7;
        int h = pr * 8 + pi, w = pc * 8 + pj;
        val = d_rays[((size_t)v * 65536 + h * 256 + w) * 6 + ch];
    }
    d_xinref[idx] = val;
}

__global__ void xintar_kernel() {
    int idx = blockIdx.x * 256 + threadIdx.x;
    if (idx >= 1024 * 384) return;
    int tok = idx / 384, f = idx % 384;
    int pr = tok >> 5, pc = tok & 31;
    int ch = f % 6, pp = f / 6;
    int pi = pp >> 3, pj = pp & 7;
    int h = pr * 8 + pi, w = pc * 8 + pj;
    d_xintar[idx] = d_rays[((size_t)2 * 65536 + h * 256 + w) * 6 + ch];
}

// ---------------- LayerNorm ----------------
__device__ __forceinline__ float block_sum(float v) {
    __shared__ float red[32];
    int lane = threadIdx.x & 31, wid = threadIdx.x >> 5;
#pragma unroll
    for (int o = 16; o; o >>= 1) v += __shfl_xor_sync(0xffffffffu, v, o);
    if (lane == 0) red[wid] = v;
    __syncthreads();
    if (wid == 0) {
        float r = (lane < 8) ? red[lane] : 0.f;
#pragma unroll
        for (int o = 4; o; o >>= 1) r += __shfl_xor_sync(0xffffffffu, r, o);
        if (lane == 0) red[0] = r;
    }
    __syncthreads();
    float out = red[0];
    __syncthreads();
    return out;
}

__global__ void ln_kernel(const float* __restrict__ x, const float* __restrict__ g,
                          float* __restrict__ out) {
    int s = blockIdx.x;
    const float* xr = x + (size_t)s * DIM;
    int t = threadIdx.x;
    float v0 = xr[t], v1 = xr[t + 256], v2 = xr[t + 512];
    float mu = block_sum(v0 + v1 + v2) * (1.0f / DIM);
    float e0 = v0 - mu, e1 = v1 - mu, e2 = v2 - mu;
    float var = block_sum(e0 * e0 + e1 * e1 + e2 * e2) * (1.0f / DIM);
    float rstd = rsqrtf(var + 1e-5f);
    float* orow = out + (size_t)s * DIM;
    orow[t]       = e0 * rstd * g[t];
    orow[t + 256] = e1 * rstd * g[t + 256];
    orow[t + 512] = e2 * rstd * g[t + 512];
}

// ---------------- TF32 MMA GEMM: C[M,N] (op)= A[M,K] @ B[N,K]^T ----------------
// 128x128 block tile, BK=16, 256 threads = 8 warps in 4(m) x 2(n), warp tile 32x64.
__global__ __launch_bounds__(256)
void sgemm_tf32(const float* __restrict__ A, const float* __restrict__ B,
                float* __restrict__ C, int M, int N, int K, int accum, int relu) {
    __shared__ float As[128][20];   // pad 20: conflict-free fragment loads
    __shared__ float Bs[128][20];
    int bm = blockIdx.y << 7, bn = blockIdx.x << 7;
    int tid = threadIdx.x;
    int lane = tid & 31, warp = tid >> 5;
    int wm = warp >> 1, wn = warp & 1;
    int gi = lane >> 2, ti = lane & 3;

    float acc[2][8][4];
#pragma unroll
    for (int mt = 0; mt < 2; mt++)
#pragma unroll
        for (int nt = 0; nt < 8; nt++)
#pragma unroll
            for (int i = 0; i < 4; i++) acc[mt][nt][i] = 0.f;

    const float* Ab = A + (size_t)bm * K;
    const float* Bb = B + (size_t)bn * K;
    int r0 = tid >> 2;               // 0..63
    int c4 = (tid & 3) << 2;         // 0,4,8,12

    float4 sA0, sA1, sB0, sB1;
    // prologue load k0 = 0
    sA0 = *(const float4*)(Ab + (size_t)r0 * K + c4);
    sA1 = *(const float4*)(Ab + (size_t)(r0 + 64) * K + c4);
    sB0 = *(const float4*)(Bb + (size_t)r0 * K + c4);
    sB1 = *(const float4*)(Bb + (size_t)(r0 + 64) * K + c4);
    As[r0][c4+0]=__uint_as_float(f2tf(sA0.x)); As[r0][c4+1]=__uint_as_float(f2tf(sA0.y));
    As[r0][c4+2]=__uint_as_float(f2tf(sA0.z)); As[r0][c4+3]=__uint_as_float(f2tf(sA0.w));
    As[r0+64][c4+0]=__uint_as_float(f2tf(sA1.x)); As[r0+64][c4+1]=__uint_as_float(f2tf(sA1.y));
    As[r0+64][c4+2]=__uint_as_float(f2tf(sA1.z)); As[r0+64][c4+3]=__uint_as_float(f2tf(sA1.w));
    Bs[r0][c4+0]=__uint_as_float(f2tf(sB0.x)); Bs[r0][c4+1]=__uint_as_float(f2tf(sB0.y));
    Bs[r0][c4+2]=__uint_as_float(f2tf(sB0.z)); Bs[r0][c4+3]=__uint_as_float(f2tf(sB0.w));
    Bs[r0+64][c4+0]=__uint_as_float(f2tf(sB1.x)); Bs[r0+64][c4+1]=__uint_as_float(f2tf(sB1.y));
    Bs[r0+64][c4+2]=__uint_as_float(f2tf(sB1.z)); Bs[r0+64][c4+3]=__uint_as_float(f2tf(sB1.w));
    __syncthreads();

    for (int k0 = 16; ; k0 += 16) {
        bool more = (k0 < K);
        if (more) {
            sA0 = *(const float4*)(Ab + (size_t)r0 * K + k0 + c4);
            sA1 = *(const float4*)(Ab + (size_t)(r0 + 64) * K + k0 + c4);
            sB0 = *(const float4*)(Bb + (size_t)r0 * K + k0 + c4);
            sB1 = *(const float4*)(Bb + (size_t)(r0 + 64) * K + k0 + c4);
        }
        // compute on current smem tile
#pragma unroll
        for (int kk = 0; kk < 16; kk += 8) {
            unsigned af[2][4];
#pragma unroll
            for (int mt = 0; mt < 2; mt++) {
                int row = wm * 32 + mt * 16 + gi;
                af[mt][0] = __float_as_uint(As[row][kk + ti]);
                af[mt][1] = __float_as_uint(As[row + 8][kk + ti]);
                af[mt][2] = __float_as_uint(As[row][kk + ti + 4]);
                af[mt][3] = __float_as_uint(As[row + 8][kk + ti + 4]);
            }
            unsigned bfr[8][2];
#pragma unroll
            for (int nt = 0; nt < 8; nt++) {
                int rn = wn * 64 + nt * 8 + gi;
                bfr[nt][0] = __float_as_uint(Bs[rn][kk + ti]);
                bfr[nt][1] = __float_as_uint(Bs[rn][kk + ti + 4]);
            }
#pragma unroll
            for (int mt = 0; mt < 2; mt++)
#pragma unroll
                for (int nt = 0; nt < 8; nt++)
                    mma_tf32(acc[mt][nt], af[mt], bfr[nt]);
        }
        if (!more) break;
        __syncthreads();
        As[r0][c4+0]=__uint_as_float(f2tf(sA0.x)); As[r0][c4+1]=__uint_as_float(f2tf(sA0.y));
        As[r0][c4+2]=__uint_as_float(f2tf(sA0.z)); As[r0][c4+3]=__uint_as_float(f2tf(sA0.w));
        As[r0+64][c4+0]=__uint_as_float(f2tf(sA1.x)); As[r0+64][c4+1]=__uint_as_float(f2tf(sA1.y));
        As[r0+64][c4+2]=__uint_as_float(f2tf(sA1.z)); As[r0+64][c4+3]=__uint_as_float(f2tf(sA1.w));
        Bs[r0][c4+0]=__uint_as_float(f2tf(sB0.x)); Bs[r0][c4+1]=__uint_as_float(f2tf(sB0.y));
        Bs[r0][c4+2]=__uint_as_float(f2tf(sB0.z)); Bs[r0][c4+3]=__uint_as_float(f2tf(sB0.w));
        Bs[r0+64][c4+0]=__uint_as_float(f2tf(sB1.x)); Bs[r0+64][c4+1]=__uint_as_float(f2tf(sB1.y));
        Bs[r0+64][c4+2]=__uint_as_float(f2tf(sB1.z)); Bs[r0+64][c4+3]=__uint_as_float(f2tf(sB1.w));
        __syncthreads();
    }

#pragma unroll
    for (int mt = 0; mt < 2; mt++) {
#pragma unroll
        for (int nt = 0; nt < 8; nt++) {
            int rr = bm + wm * 32 + mt * 16 + gi;
            int cc = bn + wn * 64 + nt * 8 + ti * 2;
            float v0 = acc[mt][nt][0], v1 = acc[mt][nt][1];
            float v2 = acc[mt][nt][2], v3 = acc[mt][nt][3];
            if (relu) { v0 = fmaxf(v0, 0.f); v1 = fmaxf(v1, 0.f);
                        v2 = fmaxf(v2, 0.f); v3 = fmaxf(v3, 0.f); }
            float* p0 = C + (size_t)rr * N + cc;
            float* p1 = C + (size_t)(rr + 8) * N + cc;
            if (accum) { v0 += p0[0]; v1 += p0[1]; v2 += p1[0]; v3 += p1[1]; }
            p0[0] = v0; p0[1] = v1; p1[0] = v2; p1[1] = v3;
        }
    }
}

// 64x64 tile fp32 variant for N=192 projection (tiny)
__global__ __launch_bounds__(256)
void sgemm64(const float* __restrict__ A, const float* __restrict__ B,
             float* __restrict__ C, int M, int N, int K) {
    __shared__ float As[16][68];
    __shared__ float Bs[16][68];
    int bm = blockIdx.y << 6, bn = blockIdx.x << 6;
    int tid = threadIdx.x;
    int tx = tid & 15, ty = tid >> 4;
    float acc[4][4];
#pragma unroll
    for (int i = 0; i < 4; i++)
#pragma unroll
        for (int j = 0; j < 4; j++) acc[i][j] = 0.f;
    int row = tid >> 2, kq = (tid & 3) << 2;
    const float* Ab = A + (size_t)bm * K;
    const float* Bb = B + (size_t)bn * K;
    for (int k0 = 0; k0 < K; k0 += 16) {
        __syncthreads();
        float4 a = *(const float4*)(Ab + (size_t)row * K + k0 + kq);
        As[kq + 0][row] = a.x; As[kq + 1][row] = a.y;
        As[kq + 2][row] = a.z; As[kq + 3][row] = a.w;
        float4 b = *(const float4*)(Bb + (size_t)row * K + k0 + kq);
        Bs[kq + 0][row] = b.x; Bs[kq + 1][row] = b.y;
        Bs[kq + 2][row] = b.z; Bs[kq + 3][row] = b.w;
        __syncthreads();
#pragma unroll
        for (int k = 0; k < 16; k++) {
            float4 a4 = *(const float4*)&As[k][ty * 4];
            float4 b4 = *(const float4*)&Bs[k][tx * 4];
            float av[4] = {a4.x, a4.y, a4.z, a4.w};
            float bv[4] = {b4.x, b4.y, b4.z, b4.w};
#pragma unroll
            for (int i = 0; i < 4; i++)
#pragma unroll
                for (int j = 0; j < 4; j++) acc[i][j] += av[i] * bv[j];
        }
    }
#pragma unroll
    for (int i = 0; i < 4; i++) {
        float* cp = C + (size_t)(bm + ty * 4 + i) * N + bn + tx * 4;
#pragma unroll
        for (int j = 0; j < 4; j++) cp[j] = acc[i][j];
    }
}

// ---------------- per-token 4x4 camera transform ----------------
__global__ void camtf_kernel(float* __restrict__ x, const float* __restrict__ Mb,
                             int ncols) {
    int ng = ncols >> 2;
    int idx = blockIdx.x * 256 + threadIdx.x;
    if (idx >= SEQ * ng) return;
    int s = idx / ng, g = idx % ng;
    const float* M = Mb + (size_t)(s >> 10) * 16;
    float4 v = *(float4*)(x + (size_t)s * ncols + g * 4);
    float y0 = M[0]  * v.x + M[1]  * v.y + M[2]  * v.z + M[3]  * v.w;
    float y1 = M[4]  * v.x + M[5]  * v.y + M[6]  * v.z + M[7]  * v.w;
    float y2 = M[8]  * v.x + M[9]  * v.y + M[10] * v.z + M[11] * v.w;
    float y3 = M[12] * v.x + M[13] * v.y + M[14] * v.z + M[15] * v.w;
    *(float4*)(x + (size_t)s * ncols + g * 4) = make_float4(y0, y1, y2, y3);
}

// ---------------- flash attention, TF32 MMA ----------------
// grid (48 q-tiles, 16 heads), 128 threads = 4 warps, each warp owns 16 q rows.
__global__ __launch_bounds__(128)
void attn_mma() {
    __shared__ float Ks[64][52];   // pad 52: conflict-free B-frag loads (8r x 4c)
    __shared__ float Vs[64][56];   // pad 56: conflict-free B-frag loads (4r x 8c)
    __shared__ float Ps[64][68];   // pad 68: conflict-free A-frag loads (8r x 4c)
    int h = blockIdx.y, qt = blockIdx.x;
    int tid = threadIdx.x, lane = tid & 31, warp = tid >> 5;
    int gi = lane >> 2, ti = lane & 3;
    int hb = h * HDIM;
    const float scale = 0.14433756729740643f;   // 1/sqrt(48)

    // preload Q fragments (scaled, tf32)
    unsigned qf[6][4];
    int qrow0 = qt * 64 + warp * 16 + gi;
#pragma unroll
    for (int ks = 0; ks < 6; ks++) {
        int c = hb + ks * 8 + ti;
        qf[ks][0] = f2tf(d_qkv[(size_t)qrow0 * 2304 + c] * scale);
        qf[ks][1] = f2tf(d_qkv[(size_t)(qrow0 + 8) * 2304 + c] * scale);
        qf[ks][2] = f2tf(d_qkv[(size_t)qrow0 * 2304 + c + 4] * scale);
        qf[ks][3] = f2tf(d_qkv[(size_t)(qrow0 + 8) * 2304 + c + 4] * scale);
    }

    float accO[6][4];
#pragma unroll
    for (int nt = 0; nt < 6; nt++)
#pragma unroll
        for (int i = 0; i < 4; i++) accO[nt][i] = 0.f;
    float mrow[2] = {-1e30f, -1e30f};
    float lrow[2] = {0.f, 0.f};

    for (int kt = 0; kt < SEQ; kt += 64) {
        __syncthreads();
        // stage K and V tiles (tf32-rounded)
        for (int i = tid; i < 64 * 12; i += 128) {
            int r = i / 12, c4 = i % 12;
            const float* kp = d_qkv + (size_t)(kt + r) * 2304 + DIM + hb + c4 * 4;
            float4 k4 = *(const float4*)kp;
            float4 v4 = *(const float4*)(kp + DIM);
            Ks[r][c4*4+0] = __uint_as_float(f2tf(k4.x));
            Ks[r][c4*4+1] = __uint_as_float(f2tf(k4.y));
            Ks[r][c4*4+2] = __uint_as_float(f2tf(k4.z));
            Ks[r][c4*4+3] = __uint_as_float(f2tf(k4.w));
            Vs[r][c4*4+0] = __uint_as_float(f2tf(v4.x));
            Vs[r][c4*4+1] = __uint_as_float(f2tf(v4.y));
            Vs[r][c4*4+2] = __uint_as_float(f2tf(v4.z));
            Vs[r][c4*4+3] = __uint_as_float(f2tf(v4.w));
        }
        __syncthreads();

        // S = Q @ K^T (per warp: 16 q rows x 64 kv cols)
        float accS[8][4];
#pragma unroll
        for (int nt = 0; nt < 8; nt++)
#pragma unroll
            for (int i = 0; i < 4; i++) accS[nt][i] = 0.f;
#pragma unroll
        for (int ks = 0; ks < 6; ks++) {
            unsigned bfr[8][2];
#pragma unroll
            for (int nt = 0; nt < 8; nt++) {
                bfr[nt][0] = __float_as_uint(Ks[nt*8 + gi][ks*8 + ti]);
                bfr[nt][1] = __float_as_uint(Ks[nt*8 + gi][ks*8 + ti + 4]);
            }
#pragma unroll
            for (int nt = 0; nt < 8; nt++)
                mma_tf32(accS[nt], qf[ks], bfr[nt]);
        }

        // online softmax (rows gi and gi+8, replicated across quad lanes)
        float tmax0 = -1e30f, tmax1 = -1e30f;
#pragma unroll
        for (int nt = 0; nt < 8; nt++) {
            tmax0 = fmaxf(tmax0, fmaxf(accS[nt][0], accS[nt][1]));
            tmax1 = fmaxf(tmax1, fmaxf(accS[nt][2], accS[nt][3]));
        }
        tmax0 = fmaxf(tmax0, __shfl_xor_sync(0xffffffffu, tmax0, 1));
        tmax0 = fmaxf(tmax0, __shfl_xor_sync(0xffffffffu, tmax0, 2));
        tmax1 = fmaxf(tmax1, __shfl_xor_sync(0xffffffffu, tmax1, 1));
        tmax1 = fmaxf(tmax1, __shfl_xor_sync(0xffffffffu, tmax1, 2));
        float newm0 = fmaxf(mrow[0], tmax0);
        float newm1 = fmaxf(mrow[1], tmax1);
        float corr0 = __expf(mrow[0] - newm0);
        float corr1 = __expf(mrow[1] - newm1);
        float psum0 = 0.f, psum1 = 0.f;
#pragma unroll
        for (int nt = 0; nt < 8; nt++) {
            accS[nt][0] = __expf(accS[nt][0] - newm0); psum0 += accS[nt][0];
            accS[nt][1] = __expf(accS[nt][1] - newm0); psum0 += accS[nt][1];
            accS[nt][2] = __expf(accS[nt][2] - newm1); psum1 += accS[nt][2];
            accS[nt][3] = __expf(accS[nt][3] - newm1); psum1 += accS[nt][3];
        }
        psum0 += __shfl_xor_sync(0xffffffffu, psum0, 1);
        psum0 += __shfl_xor_sync(0xffffffffu, psum0, 2);
        psum1 += __shfl_xor_sync(0xffffffffu, psum1, 1);
        psum1 += __shfl_xor_sync(0xffffffffu, psum1, 2);
        lrow[0] = lrow[0] * corr0 + psum0;
        lrow[1] = lrow[1] * corr1 + psum1;
        mrow[0] = newm0; mrow[1] = newm1;
#pragma unroll
        for (int nt = 0; nt < 6; nt++) {
            accO[nt][0] *= corr0; accO[nt][1] *= corr0;
            accO[nt][2] *= corr1; accO[nt][3] *= corr1;
        }

        // write P to smem (tf32-rounded), per-warp region
        int pr = warp * 16 + gi;
#pragma unroll
        for (int nt = 0; nt < 8; nt++) {
            *(float2*)&Ps[pr][nt*8 + ti*2] = make_float2(
                __uint_as_float(f2tf(accS[nt][0])), __uint_as_float(f2tf(accS[nt][1])));
            *(float2*)&Ps[pr + 8][nt*8 + ti*2] = make_float2(
                __uint_as_float(f2tf(accS[nt][2])), __uint_as_float(f2tf(accS[nt][3])));
        }
        __syncwarp();

        // O += P @ V
#pragma unroll
        for (int ks2 = 0; ks2 < 8; ks2++) {
            unsigned pa[4];
            pa[0] = __float_as_uint(Ps[pr][ks2*8 + ti]);
            pa[1] = __float_as_uint(Ps[pr + 8][ks2*8 + ti]);
            pa[2] = __float_as_uint(Ps[pr][ks2*8 + ti + 4]);
            pa[3] = __float_as_uint(Ps[pr + 8][ks2*8 + ti + 4]);
#pragma unroll
            for (int nt = 0; nt < 6; nt++) {
                unsigned bfr[2];
                bfr[0] = __float_as_uint(Vs[ks2*8 + ti][nt*8 + gi]);
                bfr[1] = __float_as_uint(Vs[ks2*8 + ti + 4][nt*8 + gi]);
                mma_tf32(accO[nt], pa, bfr);
            }
        }
        __syncwarp();
    }

    // epilogue
    float inv0 = 1.f / lrow[0];
    float inv1 = 1.f / lrow[1];
    float* ob = d_o + (size_t)qrow0 * DIM + hb;
#pragma unroll
    for (int nt = 0; nt < 6; nt++) {
        int c = nt * 8 + ti * 2;
        ob[c]     = accO[nt][0] * inv0;
        ob[c + 1] = accO[nt][1] * inv0;
        ob[(size_t)8 * DIM + c]     = accO[nt][2] * inv1;
        ob[(size_t)8 * DIM + c + 1] = accO[nt][3] * inv1;
    }
}

// ---------------- unpatchify ----------------
__global__ void unpatch_kernel(float* __restrict__ out) {
    int idx = blockIdx.x * 256 + threadIdx.x;
    if (idx >= IMGSZ * IMGSZ * 3) return;
    int c = idx % 3;
    int w = (idx / 3) & 255;
    int h = idx / (IMGSZ * 3);
    int n = (h >> 3) * 32 + (w >> 3);
    int f = ((h & 7) * 8 + (w & 7)) * 3 + c;
    out[idx] = d_proj[n * 192 + f];
}

// ---------------- launcher ----------------
extern "C" void kernel_launch(void* const* d_in, const int* in_sizes, int n_in,
                              void* d_out, int out_size) {
    (void)in_sizes; (void)n_in; (void)out_size;
    const float* ref_imgs = (const float*)d_in[0];
    const float* ref_c2w  = (const float*)d_in[1];
    const float* ref_K    = (const float*)d_in[2];
    const float* tar_c2w  = (const float*)d_in[3];
    const float* tar_K    = (const float*)d_in[4];
    const float* W_in     = (const float*)d_in[5];
    const float* W_q      = (const float*)d_in[6];
    const float* W_out    = (const float*)d_in[7];
    const float* gin      = (const float*)d_in[8];
    const float* gout     = (const float*)d_in[9];
    const float* Wqkv     = (const float*)d_in[10];
    const float* Wo       = (const float*)d_in[11];
    const float* g1       = (const float*)d_in[12];
    const float* g2       = (const float*)d_in[13];
    const float* W1       = (const float*)d_in[14];
    const float* W2       = (const float*)d_in[15];
    float* out = (float*)d_out;

    float *x, *h, *qkv, *o, *f, *xinref, *xintar, *proj, *M, *Minv;
    cudaGetSymbolAddress((void**)&x,      d_x);
    cudaGetSymbolAddress((void**)&h,      d_h);
    cudaGetSymbolAddress((void**)&qkv,    d_qkv);
    cudaGetSymbolAddress((void**)&o,      d_o);
    cudaGetSymbolAddress((void**)&f,      d_f);
    cudaGetSymbolAddress((void**)&xinref, d_xinref);
    cudaGetSymbolAddress((void**)&xintar, d_xintar);
    cudaGetSymbolAddress((void**)&proj,   d_proj);
    cudaGetSymbolAddress((void**)&M,      d_M);
    cudaGetSymbolAddress((void**)&Minv,   d_Minv);

    cams_kernel<<<1, 3>>>(ref_c2w, tar_c2w);
    rays_kernel<<<768, 256>>>(ref_c2w, ref_K, tar_c2w, tar_K);
    xinref_kernel<<<4608, 256>>>(ref_imgs);
    xintar_kernel<<<1536, 256>>>();

    sgemm_tf32<<<dim3(6, 16), 256>>>(xinref, W_in, x, 2048, DIM, 576, 0, 0);
    sgemm_tf32<<<dim3(6, 8),  256>>>(xintar, W_q,  x + (size_t)2048 * DIM, 1024, DIM, 384, 0, 0);
    ln_kernel<<<SEQ, 256>>>(x, gin, x);

    for (int l = 0; l < NLAYER; l++) {
        ln_kernel<<<SEQ, 256>>>(x, g1 + (size_t)l * DIM, h);
        sgemm_tf32<<<dim3(18, 24), 256>>>(h, Wqkv + (size_t)l * 3 * DIM * DIM, qkv,
                                          SEQ, 3 * DIM, DIM, 0, 0);
        camtf_kernel<<<6912, 256>>>(qkv, M, 3 * DIM);
        attn_mma<<<dim3(48, NHEAD), 128>>>();
        camtf_kernel<<<2304, 256>>>(o, Minv, DIM);
        sgemm_tf32<<<dim3(6, 24), 256>>>(o, Wo + (size_t)l * DIM * DIM, x,
                                         SEQ, DIM, DIM, 1, 0);
        ln_kernel<<<SEQ, 256>>>(x, g2 + (size_t)l * DIM, h);
        sgemm_tf32<<<dim3(24, 24), 256>>>(h, W1 + (size_t)l * DFF * DIM, f,
                                          SEQ, DFF, DIM, 0, 1);
        sgemm_tf32<<<dim3(6, 24), 256>>>(f, W2 + (size_t)l * DIM * DFF, x,
                                         SEQ, DIM, DFF, 1, 0);
    }

    ln_kernel<<<SEQ, 256>>>(x, gout, h);
    sgemm64<<<dim3(3, 16), 256>>>(h + (size_t)2048 * DIM, W_out, proj, 1024, 192, DIM);
    unpatch_kernel<<<768, 256>>>(out);
}